// round 1
// baseline (speedup 1.0000x reference)
#include <cuda_runtime.h>
#include <math.h>

#define NMAX   (1 << 20)          // max points supported (N = 1e6 in problem)
#define NBMAX  ((NMAX + 255) / 256)
#define STATS_BLOCKS 1024

// -------- scratch (static device globals; no runtime allocation) ----------
__device__ float    g_feat_t[64 * NMAX];          // transposed xyz_feat [64][N]
__device__ float    g_out_part[NBMAX * 256];      // per-block partial sums of feat*w
__device__ float    g_stats_part[STATS_BLOCKS * 12]; // per-block min3/max3/sum3
__device__ float    g_norm[4];                    // center.xyz, scale
__device__ unsigned g_glb[64];                    // ordered-uint encoded channel max
__device__ float    g_glbc[64];                   // b3 + glb @ w3[64:128]

// -------- helpers ----------------------------------------------------------
__device__ __forceinline__ unsigned enc_f(float f) {
    unsigned u = __float_as_uint(f);
    return (u & 0x80000000u) ? ~u : (u | 0x80000000u);
}
__device__ __forceinline__ float dec_f(unsigned k) {
    return (k & 0x80000000u) ? __uint_as_float(k ^ 0x80000000u)
                             : __uint_as_float(~k);
}

__device__ __forceinline__ void layer_norm64(float (&x)[64], const float* g,
                                             const float* b, bool do_relu) {
    float s = 0.f;
#pragma unroll
    for (int j = 0; j < 64; j++) s += x[j];
    float m = s * (1.0f / 64.0f);
    float v = 0.f;
#pragma unroll
    for (int j = 0; j < 64; j++) { float d = x[j] - m; v += d * d; }
    float r = rsqrtf(v * (1.0f / 64.0f) + 1e-5f);
#pragma unroll
    for (int j = 0; j < 64; j++) {
        float y = (x[j] - m) * r * g[j] + b[j];
        x[j] = do_relu ? fmaxf(y, 0.0f) : y;
    }
}

// -------- kernel 1: per-block xyz stats ------------------------------------
__global__ void k_stats(const float* __restrict__ xyz, int n) {
    float mn0 =  INFINITY, mn1 =  INFINITY, mn2 =  INFINITY;
    float mx0 = -INFINITY, mx1 = -INFINITY, mx2 = -INFINITY;
    float s0 = 0.f, s1 = 0.f, s2 = 0.f;
    for (int i = blockIdx.x * blockDim.x + threadIdx.x; i < n;
         i += gridDim.x * blockDim.x) {
        float x0 = xyz[3 * i + 0], x1 = xyz[3 * i + 1], x2 = xyz[3 * i + 2];
        mn0 = fminf(mn0, x0); mn1 = fminf(mn1, x1); mn2 = fminf(mn2, x2);
        mx0 = fmaxf(mx0, x0); mx1 = fmaxf(mx1, x1); mx2 = fmaxf(mx2, x2);
        s0 += x0; s1 += x1; s2 += x2;
    }
#pragma unroll
    for (int o = 16; o > 0; o >>= 1) {
        mn0 = fminf(mn0, __shfl_xor_sync(0xffffffffu, mn0, o));
        mn1 = fminf(mn1, __shfl_xor_sync(0xffffffffu, mn1, o));
        mn2 = fminf(mn2, __shfl_xor_sync(0xffffffffu, mn2, o));
        mx0 = fmaxf(mx0, __shfl_xor_sync(0xffffffffu, mx0, o));
        mx1 = fmaxf(mx1, __shfl_xor_sync(0xffffffffu, mx1, o));
        mx2 = fmaxf(mx2, __shfl_xor_sync(0xffffffffu, mx2, o));
        s0 += __shfl_xor_sync(0xffffffffu, s0, o);
        s1 += __shfl_xor_sync(0xffffffffu, s1, o);
        s2 += __shfl_xor_sync(0xffffffffu, s2, o);
    }
    __shared__ float sh[8][9];
    int wid = threadIdx.x >> 5, lane = threadIdx.x & 31;
    if (lane == 0) {
        sh[wid][0] = mn0; sh[wid][1] = mn1; sh[wid][2] = mn2;
        sh[wid][3] = mx0; sh[wid][4] = mx1; sh[wid][5] = mx2;
        sh[wid][6] = s0;  sh[wid][7] = s1;  sh[wid][8] = s2;
    }
    __syncthreads();
    if (threadIdx.x == 0) {
        float r[9];
#pragma unroll
        for (int q = 0; q < 9; q++) r[q] = sh[0][q];
        for (int w = 1; w < 8; w++) {
            r[0] = fminf(r[0], sh[w][0]); r[1] = fminf(r[1], sh[w][1]);
            r[2] = fminf(r[2], sh[w][2]);
            r[3] = fmaxf(r[3], sh[w][3]); r[4] = fmaxf(r[4], sh[w][4]);
            r[5] = fmaxf(r[5], sh[w][5]);
            r[6] += sh[w][6]; r[7] += sh[w][7]; r[8] += sh[w][8];
        }
#pragma unroll
        for (int q = 0; q < 9; q++) g_stats_part[blockIdx.x * 12 + q] = r[q];
    }
}

// -------- kernel 2: finalize stats + init glb ------------------------------
__global__ void k_stats_final(int n) {
    int tid = threadIdx.x;
    float mn0 =  INFINITY, mn1 =  INFINITY, mn2 =  INFINITY;
    float mx0 = -INFINITY, mx1 = -INFINITY, mx2 = -INFINITY;
    float s0 = 0.f, s1 = 0.f, s2 = 0.f;
    for (int p = tid; p < STATS_BLOCKS; p += 256) {
        const float* r = &g_stats_part[p * 12];
        mn0 = fminf(mn0, r[0]); mn1 = fminf(mn1, r[1]); mn2 = fminf(mn2, r[2]);
        mx0 = fmaxf(mx0, r[3]); mx1 = fmaxf(mx1, r[4]); mx2 = fmaxf(mx2, r[5]);
        s0 += r[6]; s1 += r[7]; s2 += r[8];
    }
#pragma unroll
    for (int o = 16; o > 0; o >>= 1) {
        mn0 = fminf(mn0, __shfl_xor_sync(0xffffffffu, mn0, o));
        mn1 = fminf(mn1, __shfl_xor_sync(0xffffffffu, mn1, o));
        mn2 = fminf(mn2, __shfl_xor_sync(0xffffffffu, mn2, o));
        mx0 = fmaxf(mx0, __shfl_xor_sync(0xffffffffu, mx0, o));
        mx1 = fmaxf(mx1, __shfl_xor_sync(0xffffffffu, mx1, o));
        mx2 = fmaxf(mx2, __shfl_xor_sync(0xffffffffu, mx2, o));
        s0 += __shfl_xor_sync(0xffffffffu, s0, o);
        s1 += __shfl_xor_sync(0xffffffffu, s1, o);
        s2 += __shfl_xor_sync(0xffffffffu, s2, o);
    }
    __shared__ float sh[8][9];
    int wid = tid >> 5, lane = tid & 31;
    if (lane == 0) {
        sh[wid][0] = mn0; sh[wid][1] = mn1; sh[wid][2] = mn2;
        sh[wid][3] = mx0; sh[wid][4] = mx1; sh[wid][5] = mx2;
        sh[wid][6] = s0;  sh[wid][7] = s1;  sh[wid][8] = s2;
    }
    __syncthreads();
    if (tid == 0) {
        float r[9];
#pragma unroll
        for (int q = 0; q < 9; q++) r[q] = sh[0][q];
        for (int w = 1; w < 8; w++) {
            r[0] = fminf(r[0], sh[w][0]); r[1] = fminf(r[1], sh[w][1]);
            r[2] = fminf(r[2], sh[w][2]);
            r[3] = fmaxf(r[3], sh[w][3]); r[4] = fmaxf(r[4], sh[w][4]);
            r[5] = fmaxf(r[5], sh[w][5]);
            r[6] += sh[w][6]; r[7] += sh[w][7]; r[8] += sh[w][8];
        }
        float inv_n = 1.0f / (float)n;
        float dia = fmaxf(fmaxf(r[3] - r[0], r[4] - r[1]), r[5] - r[2]);
        g_norm[0] = r[6] * inv_n;
        g_norm[1] = r[7] * inv_n;
        g_norm[2] = r[8] * inv_n;
        g_norm[3] = 1.0f / (dia + 0.0001f);
    }
    if (tid < 64) g_glb[tid] = 0u;  // smaller than any encoded float
}

// -------- kernel 3: phase 1 (pts_proj1 -> xyz_feat + channel max) ----------
__global__ void __launch_bounds__(256)
k_phase1(const float* __restrict__ xyz,
         const float* __restrict__ w1, const float* __restrict__ b1,
         const float* __restrict__ ln1g, const float* __restrict__ ln1b,
         const float* __restrict__ w2, const float* __restrict__ b2,
         const float* __restrict__ ln2g, const float* __restrict__ ln2b,
         int n) {
    __shared__ float s_w1[192], s_b1[64], s_ln1g[64], s_ln1b[64];
    __shared__ float s_w2[4096], s_b2[64], s_ln2g[64], s_ln2b[64];
    __shared__ float s_norm[4];
    __shared__ unsigned s_glb[64];

    int tid = threadIdx.x;
    for (int q = tid; q < 4096; q += 256) s_w2[q] = w2[q];
    if (tid < 192) s_w1[tid] = w1[tid];
    if (tid < 64) {
        s_b1[tid] = b1[tid]; s_ln1g[tid] = ln1g[tid]; s_ln1b[tid] = ln1b[tid];
        s_b2[tid] = b2[tid]; s_ln2g[tid] = ln2g[tid]; s_ln2b[tid] = ln2b[tid];
        s_glb[tid] = 0u;
    }
    if (tid < 4) s_norm[tid] = g_norm[tid];
    __syncthreads();

    int i = blockIdx.x * 256 + tid;
    bool valid = (i < n);
    float x0 = 0.f, x1 = 0.f, x2 = 0.f;
    if (valid) {
        float scale = s_norm[3];
        x0 = (xyz[3 * i + 0] - s_norm[0]) * scale;
        x1 = (xyz[3 * i + 1] - s_norm[1]) * scale;
        x2 = (xyz[3 * i + 2] - s_norm[2]) * scale;
    }

    float h[64];
#pragma unroll
    for (int j = 0; j < 64; j++)
        h[j] = s_b1[j] + x0 * s_w1[j] + x1 * s_w1[64 + j] + x2 * s_w1[128 + j];
    layer_norm64(h, s_ln1g, s_ln1b, true);

    float o[64];
#pragma unroll
    for (int j = 0; j < 64; j++) o[j] = s_b2[j];
#pragma unroll
    for (int k = 0; k < 64; k++) {
        float hk = h[k];
        const float4* wr = (const float4*)(s_w2 + k * 64);
#pragma unroll
        for (int jv = 0; jv < 16; jv++) {
            float4 w = wr[jv];
            o[4 * jv + 0] += hk * w.x;
            o[4 * jv + 1] += hk * w.y;
            o[4 * jv + 2] += hk * w.z;
            o[4 * jv + 3] += hk * w.w;
        }
    }
    layer_norm64(o, s_ln2g, s_ln2b, false);

    if (valid) {
#pragma unroll
        for (int j = 0; j < 64; j++) g_feat_t[(size_t)j * n + i] = o[j];
    }

    // block channel-max (warp butterfly -> smem atomic -> global atomic)
    int lane = tid & 31;
#pragma unroll
    for (int j = 0; j < 64; j++) {
        float v = valid ? o[j] : -INFINITY;
#pragma unroll
        for (int off = 16; off > 0; off >>= 1)
            v = fmaxf(v, __shfl_xor_sync(0xffffffffu, v, off));
        if (lane == 0) atomicMax(&s_glb[j], enc_f(v));
    }
    __syncthreads();
    if (tid < 64) atomicMax(&g_glb[tid], s_glb[tid]);
}

// -------- kernel 4: fold glb into bias -------------------------------------
__global__ void k_glb_prep(const float* __restrict__ w3,
                           const float* __restrict__ b3) {
    int j = threadIdx.x;  // 64 threads
    float acc = b3[j];
    for (int k = 0; k < 64; k++)
        acc += dec_f(g_glb[k]) * w3[(64 + k) * 64 + j];
    g_glbc[j] = acc;
}

// -------- kernel 5: phase 2 (pts_proj2 -> w -> feat accumulation) ----------
__global__ void __launch_bounds__(256)
k_phase2(const float* __restrict__ feat,
         const float* __restrict__ w3,
         const float* __restrict__ ln3g, const float* __restrict__ ln3b,
         const float* __restrict__ w4, int n, int D) {
    __shared__ float s_w3[4096], s_gc[64], s_ln3g[64], s_ln3b[64], s_w4[64];
    __shared__ float s_w[256];

    int tid = threadIdx.x;
    for (int q = tid; q < 4096; q += 256) s_w3[q] = w3[q];  // top 64 rows
    if (tid < 64) {
        s_gc[tid] = g_glbc[tid];
        s_ln3g[tid] = ln3g[tid]; s_ln3b[tid] = ln3b[tid];
        s_w4[tid] = w4[tid];
    }
    __syncthreads();

    int i = blockIdx.x * 256 + tid;
    bool valid = (i < n);

    float f[64];
#pragma unroll
    for (int k = 0; k < 64; k++)
        f[k] = valid ? g_feat_t[(size_t)k * n + i] : 0.f;

    float o[64];
#pragma unroll
    for (int j = 0; j < 64; j++) o[j] = s_gc[j];
#pragma unroll
    for (int k = 0; k < 64; k++) {
        float fk = f[k];
        const float4* wr = (const float4*)(s_w3 + k * 64);
#pragma unroll
        for (int jv = 0; jv < 16; jv++) {
            float4 w = wr[jv];
            o[4 * jv + 0] += fk * w.x;
            o[4 * jv + 1] += fk * w.y;
            o[4 * jv + 2] += fk * w.z;
            o[4 * jv + 3] += fk * w.w;
        }
    }
    layer_norm64(o, s_ln3g, s_ln3b, true);

    float logit = 0.f;
#pragma unroll
    for (int j = 0; j < 64; j++) logit += o[j] * s_w4[j];
    float wv = valid ? (2.0f / (1.0f + expf(-logit))) : 0.f;
    s_w[tid] = wv;
    __syncthreads();

    int i0 = blockIdx.x * 256;
    int cnt = n - i0; if (cnt > 256) cnt = 256;
    for (int d = tid; d < D; d += 256) {
        float a0 = 0.f, a1 = 0.f, a2 = 0.f, a3 = 0.f;
        int ii = 0;
        for (; ii + 4 <= cnt; ii += 4) {
            a0 += feat[(size_t)(i0 + ii + 0) * D + d] * s_w[ii + 0];
            a1 += feat[(size_t)(i0 + ii + 1) * D + d] * s_w[ii + 1];
            a2 += feat[(size_t)(i0 + ii + 2) * D + d] * s_w[ii + 2];
            a3 += feat[(size_t)(i0 + ii + 3) * D + d] * s_w[ii + 3];
        }
        for (; ii < cnt; ii++)
            a0 += feat[(size_t)(i0 + ii) * D + d] * s_w[ii];
        g_out_part[(size_t)blockIdx.x * D + d] = (a0 + a1) + (a2 + a3);
    }
}

// -------- kernel 6: final fixed-order reduction -----------------------------
__global__ void k_out_final(float* __restrict__ out, int n, int nb, int D) {
    int tid = threadIdx.x;
    float inv_n = 1.0f / (float)n;
    for (int d = tid; d < D; d += 256) {
        float s = 0.f;
        for (int b = 0; b < nb; b++) s += g_out_part[(size_t)b * D + d];
        out[d] = s * inv_n;
    }
}

// -------- launch ------------------------------------------------------------
extern "C" void kernel_launch(void* const* d_in, const int* in_sizes, int n_in,
                              void* d_out, int out_size) {
    const float* feat = (const float*)d_in[0];
    const float* xyz  = (const float*)d_in[1];
    const float* w1   = (const float*)d_in[2];
    const float* b1   = (const float*)d_in[3];
    const float* ln1g = (const float*)d_in[4];
    const float* ln1b = (const float*)d_in[5];
    const float* w2   = (const float*)d_in[6];
    const float* b2   = (const float*)d_in[7];
    const float* ln2g = (const float*)d_in[8];
    const float* ln2b = (const float*)d_in[9];
    const float* w3   = (const float*)d_in[10];
    const float* b3   = (const float*)d_in[11];
    const float* ln3g = (const float*)d_in[12];
    const float* ln3b = (const float*)d_in[13];
    const float* w4   = (const float*)d_in[14];

    int n = in_sizes[1] / 3;
    int D = in_sizes[0] / n;
    int NB = (n + 255) / 256;

    k_stats<<<STATS_BLOCKS, 256>>>(xyz, n);
    k_stats_final<<<1, 256>>>(n);
    k_phase1<<<NB, 256>>>(xyz, w1, b1, ln1g, ln1b, w2, b2, ln2g, ln2b, n);
    k_glb_prep<<<1, 64>>>(w3, b3);
    k_phase2<<<NB, 256>>>(feat, w3, ln3g, ln3b, w4, n, D);
    k_out_final<<<1, 256>>>((float*)d_out, n, NB, D);
}

// round 2
// speedup vs baseline: 1.2629x; 1.2629x over previous
#include <cuda_runtime.h>
#include <math.h>

#define NMAX   (1 << 20)
#define NBMAX  ((NMAX + 255) / 256)
#define NB2MAX ((NBMAX + 127) / 128)
#define STATS_BLOCKS 1024

typedef unsigned long long ull;

// -------- scratch ----------
__device__ float    g_feat_t[64 * NMAX];            // transposed xyz_feat [64][N]
__device__ float    g_out_part[(size_t)NBMAX * 256];
__device__ float    g_out_part2[(size_t)NB2MAX * 256];
__device__ float    g_stats_part[STATS_BLOCKS * 12];
__device__ float    g_norm[4];
__device__ unsigned g_glb[64];
__device__ float    g_glbc[64];

// -------- f32x2 helpers ----------
__device__ __forceinline__ ull pack2(float lo, float hi) {
    ull r; asm("mov.b64 %0, {%1,%2};" : "=l"(r) : "f"(lo), "f"(hi)); return r;
}
__device__ __forceinline__ void unpack2(ull v, float& lo, float& hi) {
    asm("mov.b64 {%0,%1}, %2;" : "=f"(lo), "=f"(hi) : "l"(v));
}
__device__ __forceinline__ ull ffma2(ull a, ull b, ull c) {
    ull d; asm("fma.rn.f32x2 %0, %1, %2, %3;" : "=l"(d) : "l"(a), "l"(b), "l"(c));
    return d;
}

__device__ __forceinline__ unsigned enc_f(float f) {
    unsigned u = __float_as_uint(f);
    return (u & 0x80000000u) ? ~u : (u | 0x80000000u);
}
__device__ __forceinline__ float dec_f(unsigned k) {
    return (k & 0x80000000u) ? __uint_as_float(k ^ 0x80000000u)
                             : __uint_as_float(~k);
}

__device__ __forceinline__ void layer_norm64(float (&x)[64], const float* g,
                                             const float* b, bool do_relu) {
    float s = 0.f;
#pragma unroll
    for (int j = 0; j < 64; j++) s += x[j];
    float m = s * (1.0f / 64.0f);
    float v = 0.f;
#pragma unroll
    for (int j = 0; j < 64; j++) { float d = x[j] - m; v += d * d; }
    float r = rsqrtf(v * (1.0f / 64.0f) + 1e-5f);
#pragma unroll
    for (int j = 0; j < 64; j++) {
        float y = (x[j] - m) * r * g[j] + b[j];
        x[j] = do_relu ? fmaxf(y, 0.0f) : y;
    }
}

// packed 64x64 GEMV from smem weights: o2[32] += x[k] * W[k][...]
__device__ __forceinline__ void gemv64_packed(const float (&x)[64],
                                              const float* s_w, ull (&o2)[32]) {
#pragma unroll
    for (int k = 0; k < 64; k++) {
        ull xk2 = pack2(x[k], x[k]);
        const ulonglong2* wr = (const ulonglong2*)(s_w + k * 64);
#pragma unroll
        for (int jv = 0; jv < 16; jv++) {
            ulonglong2 w = wr[jv];
            o2[2 * jv + 0] = ffma2(xk2, w.x, o2[2 * jv + 0]);
            o2[2 * jv + 1] = ffma2(xk2, w.y, o2[2 * jv + 1]);
        }
    }
}

// -------- kernel 1: per-block xyz stats ------------------------------------
__global__ void k_stats(const float* __restrict__ xyz, int n) {
    float mn0 =  INFINITY, mn1 =  INFINITY, mn2 =  INFINITY;
    float mx0 = -INFINITY, mx1 = -INFINITY, mx2 = -INFINITY;
    float s0 = 0.f, s1 = 0.f, s2 = 0.f;
    for (int i = blockIdx.x * blockDim.x + threadIdx.x; i < n;
         i += gridDim.x * blockDim.x) {
        float x0 = xyz[3 * i + 0], x1 = xyz[3 * i + 1], x2 = xyz[3 * i + 2];
        mn0 = fminf(mn0, x0); mn1 = fminf(mn1, x1); mn2 = fminf(mn2, x2);
        mx0 = fmaxf(mx0, x0); mx1 = fmaxf(mx1, x1); mx2 = fmaxf(mx2, x2);
        s0 += x0; s1 += x1; s2 += x2;
    }
#pragma unroll
    for (int o = 16; o > 0; o >>= 1) {
        mn0 = fminf(mn0, __shfl_xor_sync(0xffffffffu, mn0, o));
        mn1 = fminf(mn1, __shfl_xor_sync(0xffffffffu, mn1, o));
        mn2 = fminf(mn2, __shfl_xor_sync(0xffffffffu, mn2, o));
        mx0 = fmaxf(mx0, __shfl_xor_sync(0xffffffffu, mx0, o));
        mx1 = fmaxf(mx1, __shfl_xor_sync(0xffffffffu, mx1, o));
        mx2 = fmaxf(mx2, __shfl_xor_sync(0xffffffffu, mx2, o));
        s0 += __shfl_xor_sync(0xffffffffu, s0, o);
        s1 += __shfl_xor_sync(0xffffffffu, s1, o);
        s2 += __shfl_xor_sync(0xffffffffu, s2, o);
    }
    __shared__ float sh[8][9];
    int wid = threadIdx.x >> 5, lane = threadIdx.x & 31;
    if (lane == 0) {
        sh[wid][0] = mn0; sh[wid][1] = mn1; sh[wid][2] = mn2;
        sh[wid][3] = mx0; sh[wid][4] = mx1; sh[wid][5] = mx2;
        sh[wid][6] = s0;  sh[wid][7] = s1;  sh[wid][8] = s2;
    }
    __syncthreads();
    if (threadIdx.x == 0) {
        float r[9];
#pragma unroll
        for (int q = 0; q < 9; q++) r[q] = sh[0][q];
        for (int w = 1; w < 8; w++) {
            r[0] = fminf(r[0], sh[w][0]); r[1] = fminf(r[1], sh[w][1]);
            r[2] = fminf(r[2], sh[w][2]);
            r[3] = fmaxf(r[3], sh[w][3]); r[4] = fmaxf(r[4], sh[w][4]);
            r[5] = fmaxf(r[5], sh[w][5]);
            r[6] += sh[w][6]; r[7] += sh[w][7]; r[8] += sh[w][8];
        }
#pragma unroll
        for (int q = 0; q < 9; q++) g_stats_part[blockIdx.x * 12 + q] = r[q];
    }
}

// -------- kernel 2: finalize stats + init glb ------------------------------
__global__ void k_stats_final(int n) {
    int tid = threadIdx.x;
    float mn0 =  INFINITY, mn1 =  INFINITY, mn2 =  INFINITY;
    float mx0 = -INFINITY, mx1 = -INFINITY, mx2 = -INFINITY;
    float s0 = 0.f, s1 = 0.f, s2 = 0.f;
    for (int p = tid; p < STATS_BLOCKS; p += 256) {
        const float* r = &g_stats_part[p * 12];
        mn0 = fminf(mn0, r[0]); mn1 = fminf(mn1, r[1]); mn2 = fminf(mn2, r[2]);
        mx0 = fmaxf(mx0, r[3]); mx1 = fmaxf(mx1, r[4]); mx2 = fmaxf(mx2, r[5]);
        s0 += r[6]; s1 += r[7]; s2 += r[8];
    }
#pragma unroll
    for (int o = 16; o > 0; o >>= 1) {
        mn0 = fminf(mn0, __shfl_xor_sync(0xffffffffu, mn0, o));
        mn1 = fminf(mn1, __shfl_xor_sync(0xffffffffu, mn1, o));
        mn2 = fminf(mn2, __shfl_xor_sync(0xffffffffu, mn2, o));
        mx0 = fmaxf(mx0, __shfl_xor_sync(0xffffffffu, mx0, o));
        mx1 = fmaxf(mx1, __shfl_xor_sync(0xffffffffu, mx1, o));
        mx2 = fmaxf(mx2, __shfl_xor_sync(0xffffffffu, mx2, o));
        s0 += __shfl_xor_sync(0xffffffffu, s0, o);
        s1 += __shfl_xor_sync(0xffffffffu, s1, o);
        s2 += __shfl_xor_sync(0xffffffffu, s2, o);
    }
    __shared__ float sh[8][9];
    int wid = tid >> 5, lane = tid & 31;
    if (lane == 0) {
        sh[wid][0] = mn0; sh[wid][1] = mn1; sh[wid][2] = mn2;
        sh[wid][3] = mx0; sh[wid][4] = mx1; sh[wid][5] = mx2;
        sh[wid][6] = s0;  sh[wid][7] = s1;  sh[wid][8] = s2;
    }
    __syncthreads();
    if (tid == 0) {
        float r[9];
#pragma unroll
        for (int q = 0; q < 9; q++) r[q] = sh[0][q];
        for (int w = 1; w < 8; w++) {
            r[0] = fminf(r[0], sh[w][0]); r[1] = fminf(r[1], sh[w][1]);
            r[2] = fminf(r[2], sh[w][2]);
            r[3] = fmaxf(r[3], sh[w][3]); r[4] = fmaxf(r[4], sh[w][4]);
            r[5] = fmaxf(r[5], sh[w][5]);
            r[6] += sh[w][6]; r[7] += sh[w][7]; r[8] += sh[w][8];
        }
        float inv_n = 1.0f / (float)n;
        float dia = fmaxf(fmaxf(r[3] - r[0], r[4] - r[1]), r[5] - r[2]);
        g_norm[0] = r[6] * inv_n;
        g_norm[1] = r[7] * inv_n;
        g_norm[2] = r[8] * inv_n;
        g_norm[3] = 1.0f / (dia + 0.0001f);
    }
    if (tid < 64) g_glb[tid] = 0u;
}

// -------- kernel 3: phase 1 --------------------------------------------------
__global__ void __launch_bounds__(256)
k_phase1(const float* __restrict__ xyz,
         const float* __restrict__ w1, const float* __restrict__ b1,
         const float* __restrict__ ln1g, const float* __restrict__ ln1b,
         const float* __restrict__ w2, const float* __restrict__ b2,
         const float* __restrict__ ln2g, const float* __restrict__ ln2b,
         int n) {
    __shared__ __align__(16) float s_w2[4096];
    __shared__ __align__(16) float s_b2[64];
    __shared__ float s_w1[192], s_b1[64], s_ln1g[64], s_ln1b[64];
    __shared__ float s_ln2g[64], s_ln2b[64];
    __shared__ float s_norm[4];
    __shared__ unsigned s_glb[64];

    int tid = threadIdx.x;
    for (int q = tid; q < 4096; q += 256) s_w2[q] = w2[q];
    if (tid < 192) s_w1[tid] = w1[tid];
    if (tid < 64) {
        s_b1[tid] = b1[tid]; s_ln1g[tid] = ln1g[tid]; s_ln1b[tid] = ln1b[tid];
        s_b2[tid] = b2[tid]; s_ln2g[tid] = ln2g[tid]; s_ln2b[tid] = ln2b[tid];
        s_glb[tid] = 0u;
    }
    if (tid < 4) s_norm[tid] = g_norm[tid];
    __syncthreads();

    int i = blockIdx.x * 256 + tid;
    bool valid = (i < n);
    float x0 = 0.f, x1 = 0.f, x2 = 0.f;
    if (valid) {
        float scale = s_norm[3];
        x0 = (xyz[3 * i + 0] - s_norm[0]) * scale;
        x1 = (xyz[3 * i + 1] - s_norm[1]) * scale;
        x2 = (xyz[3 * i + 2] - s_norm[2]) * scale;
    }

    float h[64];
#pragma unroll
    for (int j = 0; j < 64; j++)
        h[j] = s_b1[j] + x0 * s_w1[j] + x1 * s_w1[64 + j] + x2 * s_w1[128 + j];
    layer_norm64(h, s_ln1g, s_ln1b, true);

    ull o2[32];
    const ull* b2p = (const ull*)s_b2;
#pragma unroll
    for (int jv = 0; jv < 32; jv++) o2[jv] = b2p[jv];
    gemv64_packed(h, s_w2, o2);

    float o[64];
#pragma unroll
    for (int jv = 0; jv < 32; jv++) unpack2(o2[jv], o[2 * jv], o[2 * jv + 1]);
    layer_norm64(o, s_ln2g, s_ln2b, false);

    if (valid) {
#pragma unroll
        for (int j = 0; j < 64; j++) g_feat_t[(size_t)j * n + i] = o[j];
    }

    int lane = tid & 31;
#pragma unroll
    for (int j = 0; j < 64; j++) {
        float v = valid ? o[j] : -INFINITY;
#pragma unroll
        for (int off = 16; off > 0; off >>= 1)
            v = fmaxf(v, __shfl_xor_sync(0xffffffffu, v, off));
        if (lane == 0) atomicMax(&s_glb[j], enc_f(v));
    }
    __syncthreads();
    if (tid < 64) atomicMax(&g_glb[tid], s_glb[tid]);
}

// -------- kernel 4: fold glb into bias -------------------------------------
__global__ void k_glb_prep(const float* __restrict__ w3,
                           const float* __restrict__ b3) {
    int j = threadIdx.x;
    float acc = b3[j];
    for (int k = 0; k < 64; k++)
        acc += dec_f(g_glb[k]) * w3[(64 + k) * 64 + j];
    g_glbc[j] = acc;
}

// -------- kernel 5: phase 2 --------------------------------------------------
__global__ void __launch_bounds__(256)
k_phase2(const float* __restrict__ feat,
         const float* __restrict__ w3,
         const float* __restrict__ ln3g, const float* __restrict__ ln3b,
         const float* __restrict__ w4, int n, int D) {
    __shared__ __align__(16) float s_w3[4096];
    __shared__ __align__(16) float s_gc[64];
    __shared__ float s_ln3g[64], s_ln3b[64], s_w4[64];
    __shared__ float s_w[256];
    __shared__ float4 s_part[4][64];

    int tid = threadIdx.x;
    for (int q = tid; q < 4096; q += 256) s_w3[q] = w3[q];
    if (tid < 64) {
        s_gc[tid] = g_glbc[tid];
        s_ln3g[tid] = ln3g[tid]; s_ln3b[tid] = ln3b[tid];
        s_w4[tid] = w4[tid];
    }
    __syncthreads();

    int i = blockIdx.x * 256 + tid;
    bool valid = (i < n);

    float f[64];
#pragma unroll
    for (int k = 0; k < 64; k++)
        f[k] = valid ? g_feat_t[(size_t)k * n + i] : 0.f;

    ull o2[32];
    const ull* gcp = (const ull*)s_gc;
#pragma unroll
    for (int jv = 0; jv < 32; jv++) o2[jv] = gcp[jv];
    gemv64_packed(f, s_w3, o2);

    float o[64];
#pragma unroll
    for (int jv = 0; jv < 32; jv++) unpack2(o2[jv], o[2 * jv], o[2 * jv + 1]);
    layer_norm64(o, s_ln3g, s_ln3b, true);

    float logit = 0.f;
#pragma unroll
    for (int j = 0; j < 64; j++) logit += o[j] * s_w4[j];
    float wv = valid ? (2.0f / (1.0f + expf(-logit))) : 0.f;
    s_w[tid] = wv;
    __syncthreads();

    // feat accumulation: 4 row-groups x 64 float4 columns (assumes D == 256)
    int c = tid & 63;
    int g = tid >> 6;
    const float4* fp = (const float4*)feat;
    float4 acc = make_float4(0.f, 0.f, 0.f, 0.f);
    int rbase = blockIdx.x * 256 + g * 64;
#pragma unroll 8
    for (int ii = 0; ii < 64; ii++) {
        int r = rbase + ii;
        if (r < n) {
            float4 v = fp[(size_t)r * 64 + c];
            float ww = s_w[g * 64 + ii];
            acc.x = fmaf(v.x, ww, acc.x);
            acc.y = fmaf(v.y, ww, acc.y);
            acc.z = fmaf(v.z, ww, acc.z);
            acc.w = fmaf(v.w, ww, acc.w);
        }
    }
    s_part[g][c] = acc;
    __syncthreads();

    if (tid < 64) {
        float4 a = s_part[0][tid];
        float4 b = s_part[1][tid];
        float4 cc = s_part[2][tid];
        float4 d = s_part[3][tid];
        float4 r;
        r.x = (a.x + b.x) + (cc.x + d.x);
        r.y = (a.y + b.y) + (cc.y + d.y);
        r.z = (a.z + b.z) + (cc.z + d.z);
        r.w = (a.w + b.w) + (cc.w + d.w);
        ((float4*)g_out_part)[(size_t)blockIdx.x * 64 + tid] = r;
    }
}

// -------- kernel 6a: mid reduction (128 blocks of partials each) ------------
__global__ void k_out_mid(int nb) {
    int b0 = blockIdx.x * 128;
    int bmax = nb - b0; if (bmax > 128) bmax = 128;
    int d = threadIdx.x;  // 256
    float a0 = 0.f, a1 = 0.f, a2 = 0.f, a3 = 0.f;
    int b = 0;
    for (; b + 4 <= bmax; b += 4) {
        a0 += g_out_part[(size_t)(b0 + b + 0) * 256 + d];
        a1 += g_out_part[(size_t)(b0 + b + 1) * 256 + d];
        a2 += g_out_part[(size_t)(b0 + b + 2) * 256 + d];
        a3 += g_out_part[(size_t)(b0 + b + 3) * 256 + d];
    }
    for (; b < bmax; b++)
        a0 += g_out_part[(size_t)(b0 + b) * 256 + d];
    g_out_part2[(size_t)blockIdx.x * 256 + d] = (a0 + a1) + (a2 + a3);
}

// -------- kernel 6b: final ---------------------------------------------------
__global__ void k_out_final(float* __restrict__ out, int n, int nb2) {
    int d = threadIdx.x;
    float inv_n = 1.0f / (float)n;
    float s = 0.f;
    for (int b = 0; b < nb2; b++) s += g_out_part2[(size_t)b * 256 + d];
    out[d] = s * inv_n;
}

// -------- launch ------------------------------------------------------------
extern "C" void kernel_launch(void* const* d_in, const int* in_sizes, int n_in,
                              void* d_out, int out_size) {
    const float* feat = (const float*)d_in[0];
    const float* xyz  = (const float*)d_in[1];
    const float* w1   = (const float*)d_in[2];
    const float* b1   = (const float*)d_in[3];
    const float* ln1g = (const float*)d_in[4];
    const float* ln1b = (const float*)d_in[5];
    const float* w2   = (const float*)d_in[6];
    const float* b2   = (const float*)d_in[7];
    const float* ln2g = (const float*)d_in[8];
    const float* ln2b = (const float*)d_in[9];
    const float* w3   = (const float*)d_in[10];
    const float* b3   = (const float*)d_in[11];
    const float* ln3g = (const float*)d_in[12];
    const float* ln3b = (const float*)d_in[13];
    const float* w4   = (const float*)d_in[14];

    int n = in_sizes[1] / 3;
    int D = in_sizes[0] / n;
    int NB = (n + 255) / 256;
    int NB2 = (NB + 127) / 128;

    k_stats<<<STATS_BLOCKS, 256>>>(xyz, n);
    k_stats_final<<<1, 256>>>(n);
    k_phase1<<<NB, 256>>>(xyz, w1, b1, ln1g, ln1b, w2, b2, ln2g, ln2b, n);
    k_glb_prep<<<1, 64>>>(w3, b3);
    k_phase2<<<NB, 256>>>(feat, w3, ln3g, ln3b, w4, n, D);
    k_out_mid<<<NB2, 256>>>(NB);
    k_out_final<<<1, 256>>>((float*)d_out, n, NB2);
}

// round 3
// speedup vs baseline: 1.4188x; 1.1234x over previous
#include <cuda_runtime.h>
#include <math.h>

#define NMAX   (1 << 20)
#define NBMAX  ((NMAX + 127) / 128)
#define NB2MAX ((NBMAX + 127) / 128)
#define STATS_BLOCKS 1024

typedef unsigned long long ull;

// -------- scratch ----------
__device__ float    g_feat_t[64 * NMAX];            // transposed xyz_feat [64][N]
__device__ float    g_out_part[(size_t)NBMAX * 256];
__device__ float    g_out_part2[(size_t)NB2MAX * 256];
__device__ float    g_stats_part[STATS_BLOCKS * 12];
__device__ float    g_norm[4];
__device__ unsigned g_glb[64];
__device__ float    g_glbc[64];

// -------- f32x2 helpers ----------
__device__ __forceinline__ ull pack2(float lo, float hi) {
    ull r; asm("mov.b64 %0, {%1,%2};" : "=l"(r) : "f"(lo), "f"(hi)); return r;
}
__device__ __forceinline__ void unpack2(ull v, float& lo, float& hi) {
    asm("mov.b64 {%0,%1}, %2;" : "=f"(lo), "=f"(hi) : "l"(v));
}
__device__ __forceinline__ ull ffma2(ull a, ull b, ull c) {
    ull d; asm("fma.rn.f32x2 %0, %1, %2, %3;" : "=l"(d) : "l"(a), "l"(b), "l"(c));
    return d;
}

__device__ __forceinline__ unsigned enc_f(float f) {
    unsigned u = __float_as_uint(f);
    return (u & 0x80000000u) ? ~u : (u | 0x80000000u);
}
__device__ __forceinline__ float dec_f(unsigned k) {
    return (k & 0x80000000u) ? __uint_as_float(k ^ 0x80000000u)
                             : __uint_as_float(~k);
}

// tree LayerNorm: pairwise sums (latency 6 levels instead of 64-chain)
__device__ __forceinline__ void layer_norm64(float (&x)[64], const float* g,
                                             const float* b, bool do_relu) {
    float s[32], q[32];
#pragma unroll
    for (int j = 0; j < 32; j++) {
        s[j] = x[j] + x[j + 32];
        q[j] = fmaf(x[j], x[j], x[j + 32] * x[j + 32]);
    }
#pragma unroll
    for (int off = 16; off > 0; off >>= 1) {
#pragma unroll
        for (int j = 0; j < off; j++) { s[j] += s[j + off]; q[j] += q[j + off]; }
    }
    float m = s[0] * (1.0f / 64.0f);
    float v = fmaf(-m, m, q[0] * (1.0f / 64.0f));
    float r = rsqrtf(fmaxf(v, 0.0f) + 1e-5f);
#pragma unroll
    for (int j = 0; j < 64; j++) {
        float t = (x[j] - m) * r;
        float y = fmaf(t, g[j], b[j]);
        x[j] = do_relu ? fmaxf(y, 0.0f) : y;
    }
}

// packed 64x64 GEMV from smem weights: o2[32] += x[k] * W[k][...]
__device__ __forceinline__ void gemv64_packed(const float (&x)[64],
                                              const float* s_w, ull (&o2)[32]) {
#pragma unroll
    for (int k = 0; k < 64; k++) {
        ull xk2 = pack2(x[k], x[k]);
        const ulonglong2* wr = (const ulonglong2*)(s_w + k * 64);
#pragma unroll
        for (int jv = 0; jv < 16; jv++) {
            ulonglong2 w = wr[jv];
            o2[2 * jv + 0] = ffma2(xk2, w.x, o2[2 * jv + 0]);
            o2[2 * jv + 1] = ffma2(xk2, w.y, o2[2 * jv + 1]);
        }
    }
}

// -------- kernel 1: per-block xyz stats ------------------------------------
__global__ void k_stats(const float* __restrict__ xyz, int n) {
    float mn0 =  INFINITY, mn1 =  INFINITY, mn2 =  INFINITY;
    float mx0 = -INFINITY, mx1 = -INFINITY, mx2 = -INFINITY;
    float s0 = 0.f, s1 = 0.f, s2 = 0.f;
    for (int i = blockIdx.x * blockDim.x + threadIdx.x; i < n;
         i += gridDim.x * blockDim.x) {
        float x0 = xyz[3 * i + 0], x1 = xyz[3 * i + 1], x2 = xyz[3 * i + 2];
        mn0 = fminf(mn0, x0); mn1 = fminf(mn1, x1); mn2 = fminf(mn2, x2);
        mx0 = fmaxf(mx0, x0); mx1 = fmaxf(mx1, x1); mx2 = fmaxf(mx2, x2);
        s0 += x0; s1 += x1; s2 += x2;
    }
#pragma unroll
    for (int o = 16; o > 0; o >>= 1) {
        mn0 = fminf(mn0, __shfl_xor_sync(0xffffffffu, mn0, o));
        mn1 = fminf(mn1, __shfl_xor_sync(0xffffffffu, mn1, o));
        mn2 = fminf(mn2, __shfl_xor_sync(0xffffffffu, mn2, o));
        mx0 = fmaxf(mx0, __shfl_xor_sync(0xffffffffu, mx0, o));
        mx1 = fmaxf(mx1, __shfl_xor_sync(0xffffffffu, mx1, o));
        mx2 = fmaxf(mx2, __shfl_xor_sync(0xffffffffu, mx2, o));
        s0 += __shfl_xor_sync(0xffffffffu, s0, o);
        s1 += __shfl_xor_sync(0xffffffffu, s1, o);
        s2 += __shfl_xor_sync(0xffffffffu, s2, o);
    }
    __shared__ float sh[8][9];
    int wid = threadIdx.x >> 5, lane = threadIdx.x & 31;
    if (lane == 0) {
        sh[wid][0] = mn0; sh[wid][1] = mn1; sh[wid][2] = mn2;
        sh[wid][3] = mx0; sh[wid][4] = mx1; sh[wid][5] = mx2;
        sh[wid][6] = s0;  sh[wid][7] = s1;  sh[wid][8] = s2;
    }
    __syncthreads();
    if (threadIdx.x == 0) {
        float r[9];
#pragma unroll
        for (int q = 0; q < 9; q++) r[q] = sh[0][q];
        for (int w = 1; w < 8; w++) {
            r[0] = fminf(r[0], sh[w][0]); r[1] = fminf(r[1], sh[w][1]);
            r[2] = fminf(r[2], sh[w][2]);
            r[3] = fmaxf(r[3], sh[w][3]); r[4] = fmaxf(r[4], sh[w][4]);
            r[5] = fmaxf(r[5], sh[w][5]);
            r[6] += sh[w][6]; r[7] += sh[w][7]; r[8] += sh[w][8];
        }
#pragma unroll
        for (int q = 0; q < 9; q++) g_stats_part[blockIdx.x * 12 + q] = r[q];
    }
}

// -------- kernel 2: finalize stats + init glb ------------------------------
__global__ void k_stats_final(int n) {
    int tid = threadIdx.x;
    float mn0 =  INFINITY, mn1 =  INFINITY, mn2 =  INFINITY;
    float mx0 = -INFINITY, mx1 = -INFINITY, mx2 = -INFINITY;
    float s0 = 0.f, s1 = 0.f, s2 = 0.f;
    for (int p = tid; p < STATS_BLOCKS; p += 256) {
        const float* r = &g_stats_part[p * 12];
        mn0 = fminf(mn0, r[0]); mn1 = fminf(mn1, r[1]); mn2 = fminf(mn2, r[2]);
        mx0 = fmaxf(mx0, r[3]); mx1 = fmaxf(mx1, r[4]); mx2 = fmaxf(mx2, r[5]);
        s0 += r[6]; s1 += r[7]; s2 += r[8];
    }
#pragma unroll
    for (int o = 16; o > 0; o >>= 1) {
        mn0 = fminf(mn0, __shfl_xor_sync(0xffffffffu, mn0, o));
        mn1 = fminf(mn1, __shfl_xor_sync(0xffffffffu, mn1, o));
        mn2 = fminf(mn2, __shfl_xor_sync(0xffffffffu, mn2, o));
        mx0 = fmaxf(mx0, __shfl_xor_sync(0xffffffffu, mx0, o));
        mx1 = fmaxf(mx1, __shfl_xor_sync(0xffffffffu, mx1, o));
        mx2 = fmaxf(mx2, __shfl_xor_sync(0xffffffffu, mx2, o));
        s0 += __shfl_xor_sync(0xffffffffu, s0, o);
        s1 += __shfl_xor_sync(0xffffffffu, s1, o);
        s2 += __shfl_xor_sync(0xffffffffu, s2, o);
    }
    __shared__ float sh[8][9];
    int wid = tid >> 5, lane = tid & 31;
    if (lane == 0) {
        sh[wid][0] = mn0; sh[wid][1] = mn1; sh[wid][2] = mn2;
        sh[wid][3] = mx0; sh[wid][4] = mx1; sh[wid][5] = mx2;
        sh[wid][6] = s0;  sh[wid][7] = s1;  sh[wid][8] = s2;
    }
    __syncthreads();
    if (tid == 0) {
        float r[9];
#pragma unroll
        for (int q = 0; q < 9; q++) r[q] = sh[0][q];
        for (int w = 1; w < 8; w++) {
            r[0] = fminf(r[0], sh[w][0]); r[1] = fminf(r[1], sh[w][1]);
            r[2] = fminf(r[2], sh[w][2]);
            r[3] = fmaxf(r[3], sh[w][3]); r[4] = fmaxf(r[4], sh[w][4]);
            r[5] = fmaxf(r[5], sh[w][5]);
            r[6] += sh[w][6]; r[7] += sh[w][7]; r[8] += sh[w][8];
        }
        float inv_n = 1.0f / (float)n;
        float dia = fmaxf(fmaxf(r[3] - r[0], r[4] - r[1]), r[5] - r[2]);
        g_norm[0] = r[6] * inv_n;
        g_norm[1] = r[7] * inv_n;
        g_norm[2] = r[8] * inv_n;
        g_norm[3] = 1.0f / (dia + 0.0001f);
    }
    if (tid < 64) g_glb[tid] = 0u;
}

// -------- kernel 3: phase 1 (128 threads/block) ------------------------------
__global__ void __launch_bounds__(128)
k_phase1(const float* __restrict__ xyz,
         const float* __restrict__ w1, const float* __restrict__ b1,
         const float* __restrict__ ln1g, const float* __restrict__ ln1b,
         const float* __restrict__ w2, const float* __restrict__ b2,
         const float* __restrict__ ln2g, const float* __restrict__ ln2b,
         int n) {
    __shared__ __align__(16) float s_w2[4096];
    __shared__ __align__(16) float s_b2[64];
    __shared__ float s_w1[192], s_b1[64], s_ln1g[64], s_ln1b[64];
    __shared__ float s_ln2g[64], s_ln2b[64];
    __shared__ float s_norm[4];
    __shared__ unsigned s_glb[64];

    int tid = threadIdx.x;
    for (int q = tid; q < 4096; q += 128) s_w2[q] = w2[q];
    if (tid < 64) {
        s_w1[tid] = w1[tid]; s_w1[64 + tid] = w1[64 + tid];
        s_w1[128 + tid] = w1[128 + tid];
        s_b1[tid] = b1[tid]; s_ln1g[tid] = ln1g[tid]; s_ln1b[tid] = ln1b[tid];
        s_b2[tid] = b2[tid]; s_ln2g[tid] = ln2g[tid]; s_ln2b[tid] = ln2b[tid];
        s_glb[tid] = 0u;
    }
    if (tid < 4) s_norm[tid] = g_norm[tid];
    __syncthreads();

    int i = blockIdx.x * 128 + tid;
    bool valid = (i < n);
    float x0 = 0.f, x1 = 0.f, x2 = 0.f;
    if (valid) {
        float scale = s_norm[3];
        x0 = (xyz[3 * i + 0] - s_norm[0]) * scale;
        x1 = (xyz[3 * i + 1] - s_norm[1]) * scale;
        x2 = (xyz[3 * i + 2] - s_norm[2]) * scale;
    }

    float h[64];
#pragma unroll
    for (int j = 0; j < 64; j++)
        h[j] = fmaf(x2, s_w1[128 + j], fmaf(x1, s_w1[64 + j], fmaf(x0, s_w1[j], s_b1[j])));
    layer_norm64(h, s_ln1g, s_ln1b, true);

    ull o2[32];
    const ull* b2p = (const ull*)s_b2;
#pragma unroll
    for (int jv = 0; jv < 32; jv++) o2[jv] = b2p[jv];
    gemv64_packed(h, s_w2, o2);

    float o[64];
#pragma unroll
    for (int jv = 0; jv < 32; jv++) unpack2(o2[jv], o[2 * jv], o[2 * jv + 1]);
    layer_norm64(o, s_ln2g, s_ln2b, false);

    if (valid) {
#pragma unroll
        for (int j = 0; j < 64; j++) g_feat_t[(size_t)j * n + i] = o[j];
    }

    int lane = tid & 31;
#pragma unroll
    for (int j = 0; j < 64; j++) {
        float v = valid ? o[j] : -INFINITY;
#pragma unroll
        for (int off = 16; off > 0; off >>= 1)
            v = fmaxf(v, __shfl_xor_sync(0xffffffffu, v, off));
        if (lane == 0) atomicMax(&s_glb[j], enc_f(v));
    }
    __syncthreads();
    if (tid < 64) atomicMax(&g_glb[tid], s_glb[tid]);
}

// -------- kernel 4: fold glb into bias -------------------------------------
__global__ void k_glb_prep(const float* __restrict__ w3,
                           const float* __restrict__ b3) {
    int j = threadIdx.x;
    float acc = b3[j];
    for (int k = 0; k < 64; k++)
        acc += dec_f(g_glb[k]) * w3[(64 + k) * 64 + j];
    g_glbc[j] = acc;
}

// -------- kernel 5: phase 2 (128 threads/block) -------------------------------
__global__ void __launch_bounds__(128)
k_phase2(const float* __restrict__ feat,
         const float* __restrict__ w3,
         const float* __restrict__ ln3g, const float* __restrict__ ln3b,
         const float* __restrict__ w4, int n) {
    __shared__ __align__(16) float s_w3[4096];
    __shared__ __align__(16) float s_gc[64];
    __shared__ float s_ln3g[64], s_ln3b[64], s_w4[64];
    __shared__ float s_w[128];
    __shared__ float4 s_part[2][64];

    int tid = threadIdx.x;
    for (int q = tid; q < 4096; q += 128) s_w3[q] = w3[q];
    if (tid < 64) {
        s_gc[tid] = g_glbc[tid];
        s_ln3g[tid] = ln3g[tid]; s_ln3b[tid] = ln3b[tid];
        s_w4[tid] = w4[tid];
    }
    __syncthreads();

    int i = blockIdx.x * 128 + tid;
    bool valid = (i < n);

    float f[64];
#pragma unroll
    for (int k = 0; k < 64; k++)
        f[k] = valid ? g_feat_t[(size_t)k * n + i] : 0.f;

    ull o2[32];
    const ull* gcp = (const ull*)s_gc;
#pragma unroll
    for (int jv = 0; jv < 32; jv++) o2[jv] = gcp[jv];
    gemv64_packed(f, s_w3, o2);

    float o[64];
#pragma unroll
    for (int jv = 0; jv < 32; jv++) unpack2(o2[jv], o[2 * jv], o[2 * jv + 1]);
    layer_norm64(o, s_ln3g, s_ln3b, true);

    // logit dot: tree
    float t[32];
#pragma unroll
    for (int j = 0; j < 32; j++)
        t[j] = fmaf(o[j], s_w4[j], o[j + 32] * s_w4[j + 32]);
#pragma unroll
    for (int off = 16; off > 0; off >>= 1) {
#pragma unroll
        for (int j = 0; j < off; j++) t[j] += t[j + off];
    }
    float wv = valid ? (2.0f / (1.0f + __expf(-t[0]))) : 0.f;
    s_w[tid] = wv;
    __syncthreads();

    // feat accumulation: 2 row-groups x 64 float4 columns (D == 256)
    int c = tid & 63;
    int g = tid >> 6;
    const float4* fp = (const float4*)feat;
    float4 acc = make_float4(0.f, 0.f, 0.f, 0.f);
    int rbase = blockIdx.x * 128 + g * 64;
#pragma unroll 8
    for (int ii = 0; ii < 64; ii++) {
        int r = rbase + ii;
        if (r < n) {
            float4 v = fp[(size_t)r * 64 + c];
            float ww = s_w[g * 64 + ii];
            acc.x = fmaf(v.x, ww, acc.x);
            acc.y = fmaf(v.y, ww, acc.y);
            acc.z = fmaf(v.z, ww, acc.z);
            acc.w = fmaf(v.w, ww, acc.w);
        }
    }
    s_part[g][c] = acc;
    __syncthreads();

    if (tid < 64) {
        float4 a = s_part[0][tid];
        float4 b = s_part[1][tid];
        float4 r;
        r.x = a.x + b.x; r.y = a.y + b.y; r.z = a.z + b.z; r.w = a.w + b.w;
        ((float4*)g_out_part)[(size_t)blockIdx.x * 64 + tid] = r;
    }
}

// -------- kernel 6a: mid reduction ------------------------------------------
__global__ void k_out_mid(int nb) {
    int b0 = blockIdx.x * 128;
    int bmax = nb - b0; if (bmax > 128) bmax = 128;
    int d = threadIdx.x;  // 256
    float a0 = 0.f, a1 = 0.f, a2 = 0.f, a3 = 0.f;
    int b = 0;
    for (; b + 4 <= bmax; b += 4) {
        a0 += g_out_part[(size_t)(b0 + b + 0) * 256 + d];
        a1 += g_out_part[(size_t)(b0 + b + 1) * 256 + d];
        a2 += g_out_part[(size_t)(b0 + b + 2) * 256 + d];
        a3 += g_out_part[(size_t)(b0 + b + 3) * 256 + d];
    }
    for (; b < bmax; b++)
        a0 += g_out_part[(size_t)(b0 + b) * 256 + d];
    g_out_part2[(size_t)blockIdx.x * 256 + d] = (a0 + a1) + (a2 + a3);
}

// -------- kernel 6b: final ---------------------------------------------------
__global__ void k_out_final(float* __restrict__ out, int n, int nb2) {
    int d = threadIdx.x;
    float inv_n = 1.0f / (float)n;
    float s = 0.f;
    for (int b = 0; b < nb2; b++) s += g_out_part2[(size_t)b * 256 + d];
    out[d] = s * inv_n;
}

// -------- launch ------------------------------------------------------------
extern "C" void kernel_launch(void* const* d_in, const int* in_sizes, int n_in,
                              void* d_out, int out_size) {
    const float* feat = (const float*)d_in[0];
    const float* xyz  = (const float*)d_in[1];
    const float* w1   = (const float*)d_in[2];
    const float* b1   = (const float*)d_in[3];
    const float* ln1g = (const float*)d_in[4];
    const float* ln1b = (const float*)d_in[5];
    const float* w2   = (const float*)d_in[6];
    const float* b2   = (const float*)d_in[7];
    const float* ln2g = (const float*)d_in[8];
    const float* ln2b = (const float*)d_in[9];
    const float* w3   = (const float*)d_in[10];
    const float* b3   = (const float*)d_in[11];
    const float* ln3g = (const float*)d_in[12];
    const float* ln3b = (const float*)d_in[13];
    const float* w4   = (const float*)d_in[14];

    int n = in_sizes[1] / 3;
    int NB = (n + 127) / 128;
    int NB2 = (NB + 127) / 128;

    k_stats<<<STATS_BLOCKS, 256>>>(xyz, n);
    k_stats_final<<<1, 256>>>(n);
    k_phase1<<<NB, 128>>>(xyz, w1, b1, ln1g, ln1b, w2, b2, ln2g, ln2b, n);
    k_glb_prep<<<1, 64>>>(w3, b3);
    k_phase2<<<NB, 128>>>(feat, w3, ln3g, ln3b, w4, n);
    k_out_mid<<<NB2, 256>>>(NB);
    k_out_final<<<1, 256>>>((float*)d_out, n, NB2);
}

// round 4
// speedup vs baseline: 1.5706x; 1.1070x over previous
#include <cuda_runtime.h>
#include <math.h>

#define NMAX   (1 << 20)
#define NBMAX  ((NMAX + 127) / 128)
#define NB2MAX ((NBMAX + 127) / 128)
#define STATS_BLOCKS 1024

typedef unsigned long long ull;

// -------- scratch ----------
__device__ float    g_feat_t[64 * NMAX];            // transposed xyz_feat [64][N]
__device__ float    g_out_part[(size_t)NBMAX * 256];
__device__ float    g_out_part2[(size_t)NB2MAX * 256];
__device__ float    g_stats_part[STATS_BLOCKS * 12];
__device__ float    g_norm[4];
__device__ unsigned g_glb[64];
__device__ float    g_glbc[64];

// -------- f32x2 helpers ----------
__device__ __forceinline__ ull pack2(float lo, float hi) {
    ull r; asm("mov.b64 %0, {%1,%2};" : "=l"(r) : "f"(lo), "f"(hi)); return r;
}
__device__ __forceinline__ void unpack2(ull v, float& lo, float& hi) {
    asm("mov.b64 {%0,%1}, %2;" : "=f"(lo), "=f"(hi) : "l"(v));
}
__device__ __forceinline__ ull ffma2(ull a, ull b, ull c) {
    ull d; asm("fma.rn.f32x2 %0, %1, %2, %3;" : "=l"(d) : "l"(a), "l"(b), "l"(c));
    return d;
}

__device__ __forceinline__ unsigned enc_f(float f) {
    unsigned u = __float_as_uint(f);
    return (u & 0x80000000u) ? ~u : (u | 0x80000000u);
}
__device__ __forceinline__ float dec_f(unsigned k) {
    return (k & 0x80000000u) ? __uint_as_float(k ^ 0x80000000u)
                             : __uint_as_float(~k);
}

// LayerNorm with 16 accumulators: depth-4 chains + 4-level tree (low reg temp)
__device__ __forceinline__ void layer_norm64(float (&x)[64], const float* g,
                                             const float* b, bool do_relu) {
    float s[16], q[16];
#pragma unroll
    for (int j = 0; j < 16; j++) {
        s[j] = (x[j] + x[j + 16]) + (x[j + 32] + x[j + 48]);
        q[j] = fmaf(x[j], x[j],
               fmaf(x[j + 16], x[j + 16],
               fmaf(x[j + 32], x[j + 32], x[j + 48] * x[j + 48])));
    }
#pragma unroll
    for (int off = 8; off > 0; off >>= 1) {
#pragma unroll
        for (int j = 0; j < off; j++) { s[j] += s[j + off]; q[j] += q[j + off]; }
    }
    float m = s[0] * (1.0f / 64.0f);
    float v = fmaf(-m, m, q[0] * (1.0f / 64.0f));
    float r = rsqrtf(fmaxf(v, 0.0f) + 1e-5f);
#pragma unroll
    for (int j = 0; j < 64; j++) {
        float t = (x[j] - m) * r;
        float y = fmaf(t, g[j], b[j]);
        x[j] = do_relu ? fmaxf(y, 0.0f) : y;
    }
}

// inner step of the packed GEMV: o2 += xk * W[k][:]
__device__ __forceinline__ void gemv_step(float xk, const float* s_w_row,
                                          ull (&o2)[32]) {
    ull xk2 = pack2(xk, xk);
    const ulonglong2* wr = (const ulonglong2*)s_w_row;
#pragma unroll
    for (int jv = 0; jv < 16; jv++) {
        ulonglong2 w = wr[jv];
        o2[2 * jv + 0] = ffma2(xk2, w.x, o2[2 * jv + 0]);
        o2[2 * jv + 1] = ffma2(xk2, w.y, o2[2 * jv + 1]);
    }
}

// -------- kernel 1: per-block xyz stats ------------------------------------
__global__ void k_stats(const float* __restrict__ xyz, int n) {
    float mn0 =  INFINITY, mn1 =  INFINITY, mn2 =  INFINITY;
    float mx0 = -INFINITY, mx1 = -INFINITY, mx2 = -INFINITY;
    float s0 = 0.f, s1 = 0.f, s2 = 0.f;
    for (int i = blockIdx.x * blockDim.x + threadIdx.x; i < n;
         i += gridDim.x * blockDim.x) {
        float x0 = xyz[3 * i + 0], x1 = xyz[3 * i + 1], x2 = xyz[3 * i + 2];
        mn0 = fminf(mn0, x0); mn1 = fminf(mn1, x1); mn2 = fminf(mn2, x2);
        mx0 = fmaxf(mx0, x0); mx1 = fmaxf(mx1, x1); mx2 = fmaxf(mx2, x2);
        s0 += x0; s1 += x1; s2 += x2;
    }
#pragma unroll
    for (int o = 16; o > 0; o >>= 1) {
        mn0 = fminf(mn0, __shfl_xor_sync(0xffffffffu, mn0, o));
        mn1 = fminf(mn1, __shfl_xor_sync(0xffffffffu, mn1, o));
        mn2 = fminf(mn2, __shfl_xor_sync(0xffffffffu, mn2, o));
        mx0 = fmaxf(mx0, __shfl_xor_sync(0xffffffffu, mx0, o));
        mx1 = fmaxf(mx1, __shfl_xor_sync(0xffffffffu, mx1, o));
        mx2 = fmaxf(mx2, __shfl_xor_sync(0xffffffffu, mx2, o));
        s0 += __shfl_xor_sync(0xffffffffu, s0, o);
        s1 += __shfl_xor_sync(0xffffffffu, s1, o);
        s2 += __shfl_xor_sync(0xffffffffu, s2, o);
    }
    __shared__ float sh[8][9];
    int wid = threadIdx.x >> 5, lane = threadIdx.x & 31;
    if (lane == 0) {
        sh[wid][0] = mn0; sh[wid][1] = mn1; sh[wid][2] = mn2;
        sh[wid][3] = mx0; sh[wid][4] = mx1; sh[wid][5] = mx2;
        sh[wid][6] = s0;  sh[wid][7] = s1;  sh[wid][8] = s2;
    }
    __syncthreads();
    if (threadIdx.x == 0) {
        float r[9];
#pragma unroll
        for (int q = 0; q < 9; q++) r[q] = sh[0][q];
        for (int w = 1; w < 8; w++) {
            r[0] = fminf(r[0], sh[w][0]); r[1] = fminf(r[1], sh[w][1]);
            r[2] = fminf(r[2], sh[w][2]);
            r[3] = fmaxf(r[3], sh[w][3]); r[4] = fmaxf(r[4], sh[w][4]);
            r[5] = fmaxf(r[5], sh[w][5]);
            r[6] += sh[w][6]; r[7] += sh[w][7]; r[8] += sh[w][8];
        }
#pragma unroll
        for (int q = 0; q < 9; q++) g_stats_part[blockIdx.x * 12 + q] = r[q];
    }
}

// -------- kernel 2: finalize stats + init glb ------------------------------
__global__ void k_stats_final(int n) {
    int tid = threadIdx.x;
    float mn0 =  INFINITY, mn1 =  INFINITY, mn2 =  INFINITY;
    float mx0 = -INFINITY, mx1 = -INFINITY, mx2 = -INFINITY;
    float s0 = 0.f, s1 = 0.f, s2 = 0.f;
    for (int p = tid; p < STATS_BLOCKS; p += 256) {
        const float* r = &g_stats_part[p * 12];
        mn0 = fminf(mn0, r[0]); mn1 = fminf(mn1, r[1]); mn2 = fminf(mn2, r[2]);
        mx0 = fmaxf(mx0, r[3]); mx1 = fmaxf(mx1, r[4]); mx2 = fmaxf(mx2, r[5]);
        s0 += r[6]; s1 += r[7]; s2 += r[8];
    }
#pragma unroll
    for (int o = 16; o > 0; o >>= 1) {
        mn0 = fminf(mn0, __shfl_xor_sync(0xffffffffu, mn0, o));
        mn1 = fminf(mn1, __shfl_xor_sync(0xffffffffu, mn1, o));
        mn2 = fminf(mn2, __shfl_xor_sync(0xffffffffu, mn2, o));
        mx0 = fmaxf(mx0, __shfl_xor_sync(0xffffffffu, mx0, o));
        mx1 = fmaxf(mx1, __shfl_xor_sync(0xffffffffu, mx1, o));
        mx2 = fmaxf(mx2, __shfl_xor_sync(0xffffffffu, mx2, o));
        s0 += __shfl_xor_sync(0xffffffffu, s0, o);
        s1 += __shfl_xor_sync(0xffffffffu, s1, o);
        s2 += __shfl_xor_sync(0xffffffffu, s2, o);
    }
    __shared__ float sh[8][9];
    int wid = tid >> 5, lane = tid & 31;
    if (lane == 0) {
        sh[wid][0] = mn0; sh[wid][1] = mn1; sh[wid][2] = mn2;
        sh[wid][3] = mx0; sh[wid][4] = mx1; sh[wid][5] = mx2;
        sh[wid][6] = s0;  sh[wid][7] = s1;  sh[wid][8] = s2;
    }
    __syncthreads();
    if (tid == 0) {
        float r[9];
#pragma unroll
        for (int q = 0; q < 9; q++) r[q] = sh[0][q];
        for (int w = 1; w < 8; w++) {
            r[0] = fminf(r[0], sh[w][0]); r[1] = fminf(r[1], sh[w][1]);
            r[2] = fminf(r[2], sh[w][2]);
            r[3] = fmaxf(r[3], sh[w][3]); r[4] = fmaxf(r[4], sh[w][4]);
            r[5] = fmaxf(r[5], sh[w][5]);
            r[6] += sh[w][6]; r[7] += sh[w][7]; r[8] += sh[w][8];
        }
        float inv_n = 1.0f / (float)n;
        float dia = fmaxf(fmaxf(r[3] - r[0], r[4] - r[1]), r[5] - r[2]);
        g_norm[0] = r[6] * inv_n;
        g_norm[1] = r[7] * inv_n;
        g_norm[2] = r[8] * inv_n;
        g_norm[3] = 1.0f / (dia + 0.0001f);
    }
    if (tid < 64) g_glb[tid] = 0u;
}

// -------- kernel 3: phase 1 (128 threads; h[0:32] staged to smem) -----------
__global__ void __launch_bounds__(128)
k_phase1(const float* __restrict__ xyz,
         const float* __restrict__ w1, const float* __restrict__ b1,
         const float* __restrict__ ln1g, const float* __restrict__ ln1b,
         const float* __restrict__ w2, const float* __restrict__ b2,
         const float* __restrict__ ln2g, const float* __restrict__ ln2b,
         int n) {
    __shared__ __align__(16) float s_w2[4096];
    __shared__ float s_x[32][128];            // staged h[0:32], own-column
    __shared__ __align__(16) float s_b2[64];
    __shared__ float s_w1[192], s_b1[64], s_ln1g[64], s_ln1b[64];
    __shared__ float s_ln2g[64], s_ln2b[64];
    __shared__ float s_norm[4];
    __shared__ unsigned s_glb[64];

    int tid = threadIdx.x;
    for (int q = tid; q < 4096; q += 128) s_w2[q] = w2[q];
    if (tid < 64) {
        s_w1[tid] = w1[tid]; s_w1[64 + tid] = w1[64 + tid];
        s_w1[128 + tid] = w1[128 + tid];
        s_b1[tid] = b1[tid]; s_ln1g[tid] = ln1g[tid]; s_ln1b[tid] = ln1b[tid];
        s_b2[tid] = b2[tid]; s_ln2g[tid] = ln2g[tid]; s_ln2b[tid] = ln2b[tid];
        s_glb[tid] = 0u;
    }
    if (tid < 4) s_norm[tid] = g_norm[tid];
    __syncthreads();

    int i = blockIdx.x * 128 + tid;
    bool valid = (i < n);
    float x0 = 0.f, x1 = 0.f, x2 = 0.f;
    if (valid) {
        float scale = s_norm[3];
        x0 = (xyz[3 * i + 0] - s_norm[0]) * scale;
        x1 = (xyz[3 * i + 1] - s_norm[1]) * scale;
        x2 = (xyz[3 * i + 2] - s_norm[2]) * scale;
    }

    float h[64];
#pragma unroll
    for (int j = 0; j < 64; j++)
        h[j] = fmaf(x2, s_w1[128 + j], fmaf(x1, s_w1[64 + j], fmaf(x0, s_w1[j], s_b1[j])));
    layer_norm64(h, s_ln1g, s_ln1b, true);

    // stage first half to smem (own column; no cross-thread sharing -> no sync)
#pragma unroll
    for (int k = 0; k < 32; k++) s_x[k][tid] = h[k];
    float hh[32];
#pragma unroll
    for (int k = 0; k < 32; k++) hh[k] = h[32 + k];

    ull o2[32];
    const ull* b2p = (const ull*)s_b2;
#pragma unroll
    for (int jv = 0; jv < 32; jv++) o2[jv] = b2p[jv];
#pragma unroll
    for (int k = 0; k < 32; k++) gemv_step(s_x[k][tid], s_w2 + k * 64, o2);
#pragma unroll
    for (int k = 0; k < 32; k++) gemv_step(hh[k], s_w2 + (32 + k) * 64, o2);

    float o[64];
#pragma unroll
    for (int jv = 0; jv < 32; jv++) unpack2(o2[jv], o[2 * jv], o[2 * jv + 1]);
    layer_norm64(o, s_ln2g, s_ln2b, false);

    if (valid) {
#pragma unroll
        for (int j = 0; j < 64; j++) g_feat_t[(size_t)j * n + i] = o[j];
    }

    int lane = tid & 31;
#pragma unroll
    for (int j = 0; j < 64; j++) {
        float v = valid ? o[j] : -INFINITY;
#pragma unroll
        for (int off = 16; off > 0; off >>= 1)
            v = fmaxf(v, __shfl_xor_sync(0xffffffffu, v, off));
        if (lane == 0) atomicMax(&s_glb[j], enc_f(v));
    }
    __syncthreads();
    if (tid < 64) atomicMax(&g_glb[tid], s_glb[tid]);
}

// -------- kernel 4: fold glb into bias -------------------------------------
__global__ void k_glb_prep(const float* __restrict__ w3,
                           const float* __restrict__ b3) {
    int j = threadIdx.x;
    float acc = b3[j];
    for (int k = 0; k < 64; k++)
        acc += dec_f(g_glb[k]) * w3[(64 + k) * 64 + j];
    g_glbc[j] = acc;
}

// -------- kernel 5: phase 2 (stream f from gmem in 16-chunks) ----------------
__global__ void __launch_bounds__(128)
k_phase2(const float* __restrict__ feat,
         const float* __restrict__ w3,
         const float* __restrict__ ln3g, const float* __restrict__ ln3b,
         const float* __restrict__ w4, int n) {
    __shared__ __align__(16) float s_w3[4096];
    __shared__ __align__(16) float s_gc[64];
    __shared__ float s_ln3g[64], s_ln3b[64], s_w4[64];
    __shared__ float s_w[128];
    __shared__ float4 s_part[2][64];

    int tid = threadIdx.x;
    for (int q = tid; q < 4096; q += 128) s_w3[q] = w3[q];
    if (tid < 64) {
        s_gc[tid] = g_glbc[tid];
        s_ln3g[tid] = ln3g[tid]; s_ln3b[tid] = ln3b[tid];
        s_w4[tid] = w4[tid];
    }
    __syncthreads();

    int i = blockIdx.x * 128 + tid;

    ull o2[32];
    const ull* gcp = (const ull*)s_gc;
#pragma unroll
    for (int jv = 0; jv < 32; jv++) o2[jv] = gcp[jv];

    // GEMV with f streamed from gmem in batches of 16 (MLP=16)
#pragma unroll
    for (int kb = 0; kb < 4; kb++) {
        float fr[16];
#pragma unroll
        for (int r = 0; r < 16; r++)
            fr[r] = g_feat_t[(size_t)(kb * 16 + r) * n + i];
#pragma unroll
        for (int r = 0; r < 16; r++)
            gemv_step(fr[r], s_w3 + (kb * 16 + r) * 64, o2);
    }

    float o[64];
#pragma unroll
    for (int jv = 0; jv < 32; jv++) unpack2(o2[jv], o[2 * jv], o[2 * jv + 1]);
    layer_norm64(o, s_ln3g, s_ln3b, true);

    // logit dot: 16-acc tree
    float t[16];
#pragma unroll
    for (int j = 0; j < 16; j++)
        t[j] = fmaf(o[j], s_w4[j],
               fmaf(o[j + 16], s_w4[j + 16],
               fmaf(o[j + 32], s_w4[j + 32], o[j + 48] * s_w4[j + 48])));
#pragma unroll
    for (int off = 8; off > 0; off >>= 1) {
#pragma unroll
        for (int j = 0; j < off; j++) t[j] += t[j + off];
    }
    float wv = (i < n) ? (2.0f / (1.0f + __expf(-t[0]))) : 0.f;
    s_w[tid] = wv;
    __syncthreads();

    // feat accumulation: 2 row-groups x 64 float4 columns (D == 256)
    int c = tid & 63;
    int g = tid >> 6;
    const float4* fp = (const float4*)feat;
    float4 acc = make_float4(0.f, 0.f, 0.f, 0.f);
    int rbase = blockIdx.x * 128 + g * 64;
#pragma unroll 8
    for (int ii = 0; ii < 64; ii++) {
        int r = rbase + ii;
        if (r < n) {
            float4 v = fp[(size_t)r * 64 + c];
            float ww = s_w[g * 64 + ii];
            acc.x = fmaf(v.x, ww, acc.x);
            acc.y = fmaf(v.y, ww, acc.y);
            acc.z = fmaf(v.z, ww, acc.z);
            acc.w = fmaf(v.w, ww, acc.w);
        }
    }
    s_part[g][c] = acc;
    __syncthreads();

    if (tid < 64) {
        float4 a = s_part[0][tid];
        float4 b = s_part[1][tid];
        float4 r;
        r.x = a.x + b.x; r.y = a.y + b.y; r.z = a.z + b.z; r.w = a.w + b.w;
        ((float4*)g_out_part)[(size_t)blockIdx.x * 64 + tid] = r;
    }
}

// -------- kernel 6a: mid reduction ------------------------------------------
__global__ void k_out_mid(int nb) {
    int b0 = blockIdx.x * 128;
    int bmax = nb - b0; if (bmax > 128) bmax = 128;
    int d = threadIdx.x;  // 256
    float a0 = 0.f, a1 = 0.f, a2 = 0.f, a3 = 0.f;
    int b = 0;
    for (; b + 4 <= bmax; b += 4) {
        a0 += g_out_part[(size_t)(b0 + b + 0) * 256 + d];
        a1 += g_out_part[(size_t)(b0 + b + 1) * 256 + d];
        a2 += g_out_part[(size_t)(b0 + b + 2) * 256 + d];
        a3 += g_out_part[(size_t)(b0 + b + 3) * 256 + d];
    }
    for (; b < bmax; b++)
        a0 += g_out_part[(size_t)(b0 + b) * 256 + d];
    g_out_part2[(size_t)blockIdx.x * 256 + d] = (a0 + a1) + (a2 + a3);
}

// -------- kernel 6b: final ---------------------------------------------------
__global__ void k_out_final(float* __restrict__ out, int n, int nb2) {
    int d = threadIdx.x;
    float inv_n = 1.0f / (float)n;
    float s = 0.f;
    for (int b = 0; b < nb2; b++) s += g_out_part2[(size_t)b * 256 + d];
    out[d] = s * inv_n;
}

// -------- launch ------------------------------------------------------------
extern "C" void kernel_launch(void* const* d_in, const int* in_sizes, int n_in,
                              void* d_out, int out_size) {
    const float* feat = (const float*)d_in[0];
    const float* xyz  = (const float*)d_in[1];
    const float* w1   = (const float*)d_in[2];
    const float* b1   = (const float*)d_in[3];
    const float* ln1g = (const float*)d_in[4];
    const float* ln1b = (const float*)d_in[5];
    const float* w2   = (const float*)d_in[6];
    const float* b2   = (const float*)d_in[7];
    const float* ln2g = (const float*)d_in[8];
    const float* ln2b = (const float*)d_in[9];
    const float* w3   = (const float*)d_in[10];
    const float* b3   = (const float*)d_in[11];
    const float* ln3g = (const float*)d_in[12];
    const float* ln3b = (const float*)d_in[13];
    const float* w4   = (const float*)d_in[14];

    int n = in_sizes[1] / 3;
    int NB = (n + 127) / 128;
    int NB2 = (NB + 127) / 128;

    k_stats<<<STATS_BLOCKS, 256>>>(xyz, n);
    k_stats_final<<<1, 256>>>(n);
    k_phase1<<<NB, 128>>>(xyz, w1, b1, ln1g, ln1b, w2, b2, ln2g, ln2b, n);
    k_glb_prep<<<1, 64>>>(w3, b3);
    k_phase2<<<NB, 128>>>(feat, w3, ln3g, ln3b, w4, n);
    k_out_mid<<<NB2, 256>>>(NB);
    k_out_final<<<1, 256>>>((float*)d_out, n, NB2);
}